// round 15
// baseline (speedup 1.0000x reference)
#include <cuda_runtime.h>
#include <cuda_bf16.h>
#include <math.h>

// ---------------------------------------------------------------------------
// N=90000, D=H=128, 2H=256, E=1.44M, G=3000, P=675000.
// ---------------------------------------------------------------------------
#define MAXN 90112
#define MAXG 4096
#define MAXE 1500000

__device__ float    g_ht  [MAXN * 512];    // fp32 ht (layers 0/1) OR split hi/lo (layers 2/3)
__device__ float    g_h1  [MAXN * 128];
__device__ float    g_h2  [MAXN * 128];
__device__ float    g_mean[MAXN * 128];
__device__ float    g_ls  [MAXN * 128];
__device__ unsigned g_axh [MAXN * 64];     // pre-split (X+agg) hi
__device__ unsigned g_axl [MAXN * 64];     // pre-split (X+agg) lo
__device__ unsigned g_w1h [4 * 256 * 64];  // W1 pre-split [l][n][k2]
__device__ unsigned g_w1l [4 * 256 * 64];
__device__ unsigned g_w2h [4 * 128 * 128]; // W2 pre-split [l][n][k2]
__device__ unsigned g_w2l [4 * 128 * 128];
__device__ unsigned g_w2sh[2 * 128 * 128]; // BN-folded scaled W2 (layers 2,3)
__device__ unsigned g_w2sl[2 * 128 * 128];
__device__ float    g_b2f [2 * 128];       // BN-folded bias
__device__ float g_u   [MAXN];
__device__ float g_v   [MAXN];
__device__ float g_colsum[512];
__device__ float g_colsq [512];
__device__ float g_scale [512];
__device__ float g_shift [512];
__device__ float g_pool[MAXG];
__device__ float g_cnt [MAXG];
__device__ float g_acc [2];
__device__ int g_deg [MAXN];
__device__ int g_off [MAXN];
__device__ int g_cur [MAXN];
__device__ int g_elist[MAXE];
__device__ int g_bsum[512];
__device__ int g_bex [512];

// ---------------------------------------------------------------------------
// bf16 split + mma helpers.
// ---------------------------------------------------------------------------
__device__ __forceinline__ void bfsplit2(float e0, float e1,
                                         unsigned& wh, unsigned& wl) {
    __nv_bfloat16 h0 = __float2bfloat16_rn(e0);
    __nv_bfloat16 h1 = __float2bfloat16_rn(e1);
    __nv_bfloat16 l0 = __float2bfloat16_rn(e0 - __bfloat162float(h0));
    __nv_bfloat16 l1 = __float2bfloat16_rn(e1 - __bfloat162float(h1));
    __nv_bfloat162 vh = __nv_bfloat162(h0, h1);
    __nv_bfloat162 vl = __nv_bfloat162(l0, l1);
    wh = *(unsigned*)&vh;
    wl = *(unsigned*)&vl;
}

__device__ __forceinline__ void mma_bf16(float4& d, const unsigned* a,
                                         unsigned b0, unsigned b1) {
    asm volatile(
        "mma.sync.aligned.m16n8k16.row.col.f32.bf16.bf16.f32 "
        "{%0,%1,%2,%3},{%4,%5,%6,%7},{%8,%9},{%0,%1,%2,%3};"
        : "+f"(d.x), "+f"(d.y), "+f"(d.z), "+f"(d.w)
        : "r"(a[0]), "r"(a[1]), "r"(a[2]), "r"(a[3]), "r"(b0), "r"(b1));
}

__device__ __forceinline__ void cp16(void* dst, const void* src) {
    unsigned d = (unsigned)__cvta_generic_to_shared(dst);
    asm volatile("cp.async.cg.shared.global [%0], [%1], 16;" :: "r"(d), "l"(src));
}
#define CP_COMMIT() asm volatile("cp.async.commit_group;")
#define CP_WAIT0()  asm volatile("cp.async.wait_group 0;")
#define CP_WAIT1()  asm volatile("cp.async.wait_group 1;")

// ---------------------------------------------------------------------------
// CSR build.
// ---------------------------------------------------------------------------
__global__ void hist_k(const int* __restrict__ ei, int E, int N) {
    int i = blockIdx.x * blockDim.x + threadIdx.x;
    if (i < E) atomicAdd(&g_deg[__ldg(ei + E + i)], 1);
}

__global__ void scan1_k(int N) {
    __shared__ int red[256];
    int i = blockIdx.x * 256 + threadIdx.x;
    red[threadIdx.x] = (i < N) ? g_deg[i] : 0;
    __syncthreads();
    for (int s = 128; s > 0; s >>= 1) {
        if (threadIdx.x < s) red[threadIdx.x] += red[threadIdx.x + s];
        __syncthreads();
    }
    if (threadIdx.x == 0) g_bsum[blockIdx.x] = red[0];
}

__global__ void scan2_k(int NB) {
    __shared__ int s0[512], s1[512];
    int t = threadIdx.x;
    int v = (t < NB) ? g_bsum[t] : 0;
    s0[t] = v;
    __syncthreads();
    int* src = s0; int* dst = s1;
    for (int o = 1; o < 512; o <<= 1) {
        int x = src[t];
        if (t >= o) x += src[t - o];
        dst[t] = x;
        __syncthreads();
        int* tmp = src; src = dst; dst = tmp;
    }
    if (t < NB) g_bex[t] = src[t] - v;
}

__global__ void scan3_k(int N) {
    __shared__ int s0[256], s1[256];
    int t = threadIdx.x;
    int i = blockIdx.x * 256 + t;
    int v = (i < N) ? g_deg[i] : 0;
    s0[t] = v;
    __syncthreads();
    int* src = s0; int* dst = s1;
    for (int o = 1; o < 256; o <<= 1) {
        int x = src[t];
        if (t >= o) x += src[t - o];
        dst[t] = x;
        __syncthreads();
        int* tmp = src; src = dst; dst = tmp;
    }
    if (i < N) {
        int off = g_bex[blockIdx.x] + src[t] - v;
        g_off[i] = off;
        g_cur[i] = off;
    }
}

__global__ void fill_k(const int* __restrict__ ei, int E) {
    int i = blockIdx.x * blockDim.x + threadIdx.x;
    if (i >= E) return;
    int s = __ldg(ei + i);
    int d = __ldg(ei + E + i);
    int p = atomicAdd(&g_cur[d], 1);
    g_elist[p] = s;
}

// ---------------------------------------------------------------------------
// Weight pre-split (W1 all layers; W2 layers 0/1 used by gemm2_k).
// ---------------------------------------------------------------------------
__global__ void wsplit_k(const float* __restrict__ W1s,
                         const float* __restrict__ W2s) {
    int i = blockIdx.x * 256 + threadIdx.x;
    const int T1 = 4 * 64 * 256;
    if (i < T1) {
        int n = i & 255, k2 = (i >> 8) & 63, l = i >> 14;
        float e0 = W1s[l * 32768 + (2 * k2) * 256 + n];
        float e1 = W1s[l * 32768 + (2 * k2 + 1) * 256 + n];
        unsigned wh, wl;
        bfsplit2(e0, e1, wh, wl);
        g_w1h[l * 16384 + n * 64 + k2] = wh;
        g_w1l[l * 16384 + n * 64 + k2] = wl;
    } else {
        int j = i - T1;
        if (j < 4 * 128 * 128) {
            int n = j & 127, k2 = (j >> 7) & 127, l = j >> 14;
            float e0 = W2s[l * 32768 + (2 * k2) * 128 + n];
            float e1 = W2s[l * 32768 + (2 * k2 + 1) * 128 + n];
            unsigned wh, wl;
            bfsplit2(e0, e1, wh, wl);
            g_w2h[l * 16384 + n * 128 + k2] = wh;
            g_w2l[l * 16384 + n * 128 + k2] = wl;
        }
    }
}

// BN-fold for layers 2/3: w2s = diag(scale) @ W2 (split), b2f = shift@W2 + b2.
__global__ void w2scale_k(const float* __restrict__ W2s,
                          const float* __restrict__ b2s) {
    int i = blockIdx.x * 256 + threadIdx.x;
    if (i < 2 * 128 * 128) {
        int n = i & 127, k2 = (i >> 7) & 127, l2 = i >> 14;   // l2: 0->layer2
        int lay = l2 + 2;
        float e0 = W2s[lay * 32768 + (2 * k2) * 128 + n] * g_scale[l2 * 256 + 2 * k2];
        float e1 = W2s[lay * 32768 + (2 * k2 + 1) * 128 + n] * g_scale[l2 * 256 + 2 * k2 + 1];
        unsigned wh, wl;
        bfsplit2(e0, e1, wh, wl);
        g_w2sh[l2 * 16384 + n * 128 + k2] = wh;
        g_w2sl[l2 * 16384 + n * 128 + k2] = wl;
    } else {
        int j = i - 2 * 128 * 128;
        if (j < 256) {
            int l2 = j >> 7, n = j & 127;
            int lay = l2 + 2;
            float s = b2s[lay * 128 + n];
            for (int k = 0; k < 256; k++)
                s += g_shift[l2 * 256 + k] * W2s[lay * 32768 + k * 128 + n];
            g_b2f[l2 * 128 + n] = s;
        }
    }
}

// ---------------------------------------------------------------------------
// Gather: agg = X[own] + sum_{j in-nbrs} X[j]; write bf16 hi/lo packed.
// ---------------------------------------------------------------------------
__global__ void gather_k(const float* __restrict__ X, int N) {
    int gw   = (blockIdx.x * blockDim.x + threadIdx.x) >> 5;
    int lane = threadIdx.x & 31;
    if (gw >= N) return;
    int base = g_off[gw];
    int dg   = g_deg[gw];
    float4 acc = *(const float4*)(X + (size_t)gw * 128 + lane * 4);
    int j = 0;
    for (; j + 2 <= dg; j += 2) {
        int s0 = __ldg(g_elist + base + j);
        int s1 = __ldg(g_elist + base + j + 1);
        float4 a = *(const float4*)(X + (size_t)s0 * 128 + lane * 4);
        float4 b = *(const float4*)(X + (size_t)s1 * 128 + lane * 4);
        acc.x += a.x + b.x; acc.y += a.y + b.y;
        acc.z += a.z + b.z; acc.w += a.w + b.w;
    }
    if (j < dg) {
        int s0 = __ldg(g_elist + base + j);
        float4 a = *(const float4*)(X + (size_t)s0 * 128 + lane * 4);
        acc.x += a.x; acc.y += a.y; acc.z += a.z; acc.w += a.w;
    }
    unsigned wh0, wl0, wh1, wl1;
    bfsplit2(acc.x, acc.y, wh0, wl0);
    bfsplit2(acc.z, acc.w, wh1, wl1);
    size_t o = (size_t)gw * 64 + lane * 2;
    g_axh[o] = wh0; g_axh[o + 1] = wh1;
    g_axl[o] = wl0; g_axl[o + 1] = wl1;
}

// ---------------------------------------------------------------------------
// GEMM common: 128x128 tile, 8 warps (4m x 2n), warp 32x64, m16n8k16, BK=16.
// ---------------------------------------------------------------------------
#define BM 128
#define BN 128
#define BK 16
#define KW 136
#define SAW 20

#define MMA3(ACC, AH, AL, BH0, BH1, BL0, BL1)  \
    do { mma_bf16(ACC, AH, BH0, BH1);          \
         mma_bf16(ACC, AL, BH0, BH1);          \
         mma_bf16(ACC, AH, BL0, BL1); } while (0)

#define MMA_PHASE12(SAH, SAL, SBH, SBL)                                     \
    {                                                                       \
        unsigned ah[2][4], al[2][4];                                        \
        _Pragma("unroll")                                                   \
        for (int wm = 0; wm < 2; wm++) {                                    \
            int mr = mBase + wm * 16 + lm;                                  \
            ah[wm][0] = (SAH)[mr * 12 + lk];                                \
            ah[wm][1] = (SAH)[(mr + 8) * 12 + lk];                          \
            ah[wm][2] = (SAH)[mr * 12 + lk + 4];                            \
            ah[wm][3] = (SAH)[(mr + 8) * 12 + lk + 4];                      \
            al[wm][0] = (SAL)[mr * 12 + lk];                                \
            al[wm][1] = (SAL)[(mr + 8) * 12 + lk];                          \
            al[wm][2] = (SAL)[mr * 12 + lk + 4];                            \
            al[wm][3] = (SAL)[(mr + 8) * 12 + lk + 4];                      \
        }                                                                   \
        _Pragma("unroll")                                                   \
        for (int wn = 0; wn < 8; wn++) {                                    \
            int nc = nBase + wn * 8 + lm;                                   \
            unsigned bh0 = (SBH)[nc * 12 + lk];                             \
            unsigned bh1 = (SBH)[nc * 12 + lk + 4];                         \
            unsigned bl0 = (SBL)[nc * 12 + lk];                             \
            unsigned bl1 = (SBL)[nc * 12 + lk + 4];                         \
            _Pragma("unroll")                                               \
            for (int wm = 0; wm < 2; wm++)                                  \
                MMA3(acc[wm][wn], ah[wm], al[wm], bh0, bh1, bl0, bl1);      \
        }                                                                   \
    }

#define MMA_PHASE2(AH, AL, SBH, SBL)                                        \
    {                                                                       \
        unsigned ah[2][4], al[2][4];                                        \
        _Pragma("unroll")                                                   \
        for (int wm = 0; wm < 2; wm++) {                                    \
            int mr = mBase + wm * 16 + lm;                                  \
            ah[wm][0] = (AH)[lk * KW + mr];                                 \
            ah[wm][1] = (AH)[lk * KW + mr + 8];                             \
            ah[wm][2] = (AH)[(lk + 4) * KW + mr];                           \
            ah[wm][3] = (AH)[(lk + 4) * KW + mr + 8];                       \
            al[wm][0] = (AL)[lk * KW + mr];                                 \
            al[wm][1] = (AL)[lk * KW + mr + 8];                             \
            al[wm][2] = (AL)[(lk + 4) * KW + mr];                           \
            al[wm][3] = (AL)[(lk + 4) * KW + mr + 8];                       \
        }                                                                   \
        _Pragma("unroll")                                                   \
        for (int wn = 0; wn < 8; wn++) {                                    \
            int nc = nBase + wn * 8 + lm;                                   \
            unsigned bh0 = (SBH)[nc * 12 + lk];                             \
            unsigned bh1 = (SBH)[nc * 12 + lk + 4];                         \
            unsigned bl0 = (SBL)[nc * 12 + lk];                             \
            unsigned bl1 = (SBL)[nc * 12 + lk + 4];                         \
            _Pragma("unroll")                                               \
            for (int wm = 0; wm < 2; wm++)                                  \
                MMA3(acc[wm][wn], ah[wm], al[wm], bh0, bh1, bl0, bl1);      \
        }                                                                   \
    }

// ---------------------------------------------------------------------------
// Generic pre-split GEMM: OUT = A_split @ B_split^T + bias.
// ---------------------------------------------------------------------------
__global__ void __launch_bounds__(256) gemmp_k(
    const unsigned* __restrict__ ah, const unsigned* __restrict__ al, int lda,
    const unsigned* __restrict__ bhA, const unsigned* __restrict__ blA,
    const unsigned* __restrict__ bhB, const unsigned* __restrict__ blB, int ldb,
    int ktiles, const float* __restrict__ bias,
    int do_stats, int write_split,
    float* __restrict__ OUT, int ldo,
    unsigned* __restrict__ OH, unsigned* __restrict__ OL,
    int N) {
    extern __shared__ unsigned dsm[];
    int tid  = threadIdx.x;
    int row0 = blockIdx.y * BM;
    int n0   = blockIdx.x * BN;
    const unsigned* wsh = (n0 < 256) ? bhA : bhB;
    const unsigned* wsl = (n0 < 256) ? blA : blB;
    int nbase = (n0 < 256) ? n0 : (n0 - 256);
    int lane = tid & 31, wid = tid >> 5;
    int lk = lane & 3, lm = lane >> 2;
    int warpM = wid & 3, warpN = wid >> 2;
    int mBase = warpM * 32, nBase = warpN * 64;
    float4 acc[2][8];
    #pragma unroll
    for (int i = 0; i < 2; i++)
        #pragma unroll
        for (int j = 0; j < 8; j++) acc[i][j] = make_float4(0.f,0.f,0.f,0.f);

    auto issue = [&](int t, int st) {
        unsigned* base = dsm + st * 6144;
        int kw = t * 8;
        #pragma unroll
        for (int q = 0; q < 4; q++) {
            int c = q * 256 + tid;
            int arr = c >> 8;
            int r   = c & 255;
            int m   = r >> 1;
            int half = r & 1;
            unsigned* dst = base + arr * 1536 + m * 12 + half * 4;
            const unsigned* src;
            if (arr == 0)      src = ah + (size_t)(row0 + m) * lda + kw + half * 4;
            else if (arr == 1) src = al + (size_t)(row0 + m) * lda + kw + half * 4;
            else if (arr == 2) src = wsh + (size_t)(nbase + m) * ldb + kw + half * 4;
            else               src = wsl + (size_t)(nbase + m) * ldb + kw + half * 4;
            cp16(dst, src);
        }
        CP_COMMIT();
    };

    issue(0, 0);
    #pragma unroll 1
    for (int t = 0; t < ktiles; t++) {
        int st = t & 1;
        if (t + 1 < ktiles) {
            issue(t + 1, st ^ 1);
            CP_WAIT1();
        } else {
            CP_WAIT0();
        }
        __syncthreads();
        unsigned* B0 = dsm + st * 6144;
        MMA_PHASE12(B0, B0 + 1536, B0 + 3072, B0 + 4608)
        __syncthreads();
    }

    float psx[8]={}, psy[8]={}, pqx[8]={}, pqy[8]={};
    #pragma unroll
    for (int wn = 0; wn < 8; wn++) {
        int col = n0 + nBase + wn * 8 + 2 * lk;
        float bx = bias[col], by = bias[col + 1];
        #pragma unroll
        for (int wm = 0; wm < 2; wm++) {
            float4 d = acc[wm][wn];
            int ra = row0 + mBase + wm * 16 + lm;
            int rb = ra + 8;
            float ox = d.x + bx, oy = d.y + by;
            float oz = d.z + bx, ow = d.w + by;
            if (ra < N) {
                if (write_split) {
                    unsigned wh, wl;
                    bfsplit2(ox, oy, wh, wl);
                    OH[(size_t)ra * 256 + (col >> 1)] = wh;
                    OL[(size_t)ra * 256 + (col >> 1)] = wl;
                } else {
                    *(float2*)(OUT + (size_t)ra * ldo + col) = make_float2(ox, oy);
                }
                psx[wn] += ox; psy[wn] += oy;
                pqx[wn] += ox * ox; pqy[wn] += oy * oy;
            }
            if (rb < N) {
                if (write_split) {
                    unsigned wh, wl;
                    bfsplit2(oz, ow, wh, wl);
                    OH[(size_t)rb * 256 + (col >> 1)] = wh;
                    OL[(size_t)rb * 256 + (col >> 1)] = wl;
                } else {
                    *(float2*)(OUT + (size_t)rb * ldo + col) = make_float2(oz, ow);
                }
                psx[wn] += oz; psy[wn] += ow;
                pqx[wn] += oz * oz; pqy[wn] += ow * ow;
            }
        }
    }
    if (do_stats) {
        #pragma unroll
        for (int wn = 0; wn < 8; wn++) {
            #pragma unroll
            for (int o = 4; o <= 16; o <<= 1) {
                psx[wn] += __shfl_xor_sync(0xffffffffu, psx[wn], o);
                psy[wn] += __shfl_xor_sync(0xffffffffu, psy[wn], o);
                pqx[wn] += __shfl_xor_sync(0xffffffffu, pqx[wn], o);
                pqy[wn] += __shfl_xor_sync(0xffffffffu, pqy[wn], o);
            }
        }
        if (lane < 4) {
            #pragma unroll
            for (int wn = 0; wn < 8; wn++) {
                int col = n0 + nBase + wn * 8 + 2 * lane;
                atomicAdd(&g_colsum[col],     psx[wn]);
                atomicAdd(&g_colsum[col + 1], psy[wn]);
                atomicAdd(&g_colsq[col],      pqx[wn]);
                atomicAdd(&g_colsq[col + 1],  pqy[wn]);
            }
        }
    }
}

__global__ void bnfin_k(const float* __restrict__ gamma,
                        const float* __restrict__ beta, int N) {
    int c = blockIdx.x * blockDim.x + threadIdx.x;
    float invN = 1.0f / (float)N;
    float mu  = g_colsum[c] * invN;
    float var = g_colsq[c] * invN - mu * mu;
    float sc  = gamma[c] * rsqrtf(var + 1e-5f);
    g_scale[c] = sc;
    g_shift[c] = beta[c] - mu * sc;
}

// ---------------------------------------------------------------------------
// GEMM2 (layers 0/1, ReLU): BN transform + split fill, pre-split W2.
// ---------------------------------------------------------------------------
__global__ void __launch_bounds__(256) gemm2_k(
    const float* __restrict__ HT,
    const unsigned* __restrict__ w2h, const unsigned* __restrict__ w2l,
    const float* __restrict__ bias, float* __restrict__ OUT,
    int N, int ldh, int koff, int relu) {
    __shared__ unsigned Ah[8 * KW], Al[8 * KW];
    __shared__ unsigned Sbh[2 * 1536], Sbl[2 * 1536];
    __shared__ float Sa[128 * SAW];
    int tid  = threadIdx.x;
    int row0 = blockIdx.y * BM;
    int lane = tid & 31, wid = tid >> 5;
    int lk = lane & 3, lm = lane >> 2;
    int warpM = wid & 3, warpN = wid >> 2;
    int mBase = warpM * 32, nBase = warpN * 64;
    float4 acc[2][8];
    #pragma unroll
    for (int i = 0; i < 2; i++)
        #pragma unroll
        for (int j = 0; j < 8; j++) acc[i][j] = make_float4(0.f,0.f,0.f,0.f);

    auto issue = [&](int kk, int st) {
        #pragma unroll
        for (int q = 0; q < 4; q++) {
            int c = q * 256 + tid;
            if (c < 512) {
                int m = c >> 2, kq = (c & 3) * 4;
                cp16(Sa + m * SAW + kq,
                     HT + (size_t)(row0 + m) * ldh + koff + kk + kq);
            } else {
                int c2 = c - 512;
                int arr = c2 >> 8;
                int r = c2 & 255;
                int n = r >> 1, half = r & 1;
                const unsigned* src = (arr ? w2l : w2h)
                    + (size_t)n * 128 + kk / 2 + half * 4;
                unsigned* dst = (arr ? Sbl : Sbh) + st * 1536 + n * 12 + half * 4;
                cp16(dst, src);
            }
        }
        CP_COMMIT();
    };
    issue(0, 0);

    #pragma unroll 1
    for (int kk = 0; kk < 256; kk += BK) {
        int st = (kk >> 4) & 1;
        CP_WAIT0();
        __syncthreads();
        #pragma unroll
        for (int h = 0; h < 2; h++) {
            int idx = h * 256 + tid;
            int m  = idx & 127;
            int kq = (idx >> 7) * 4;
            float4 a = *(float4*)(Sa + m * SAW + kq);
            float4 sc4 = *(const float4*)(g_scale + koff + kk + kq);
            float4 sh4 = *(const float4*)(g_shift + koff + kk + kq);
            a.x = a.x * sc4.x + sh4.x;
            a.y = a.y * sc4.y + sh4.y;
            a.z = a.z * sc4.z + sh4.z;
            a.w = a.w * sc4.w + sh4.w;
            if (relu) {
                a.x = fmaxf(a.x, 0.f); a.y = fmaxf(a.y, 0.f);
                a.z = fmaxf(a.z, 0.f); a.w = fmaxf(a.w, 0.f);
            }
            unsigned wh0, wl0, wh1, wl1;
            bfsplit2(a.x, a.y, wh0, wl0);
            bfsplit2(a.z, a.w, wh1, wl1);
            int aw = (kq >> 1) * KW + m;
            Ah[aw] = wh0; Al[aw] = wl0;
            Ah[aw + KW] = wh1; Al[aw + KW] = wl1;
        }
        __syncthreads();
        if (kk + BK < 256) issue(kk + BK, st ^ 1);
        MMA_PHASE2(Ah, Al, Sbh + st * 1536, Sbl + st * 1536)
    }

    #pragma unroll
    for (int wn = 0; wn < 8; wn++) {
        int col = nBase + wn * 8 + 2 * lk;
        float bx = bias[col], by = bias[col + 1];
        #pragma unroll
        for (int wm = 0; wm < 2; wm++) {
            float4 d = acc[wm][wn];
            int ra = row0 + mBase + wm * 16 + lm;
            int rb = ra + 8;
            if (ra < N)
                *(float2*)(OUT + (size_t)ra * 128 + col) = make_float2(d.x + bx, d.y + by);
            if (rb < N)
                *(float2*)(OUT + (size_t)rb * 128 + col) = make_float2(d.z + bx, d.w + by);
        }
    }
}

// ---------------------------------------------------------------------------
// z epilogue and small kernels.
// ---------------------------------------------------------------------------
__global__ void z_k(const float* __restrict__ MEAN, const float* __restrict__ LS,
                    const float* __restrict__ NOISE, const int* __restrict__ batch,
                    const float* __restrict__ Wn, const float* __restrict__ Wc,
                    int N) {
    __shared__ float klred[8];
    int lane = threadIdx.x & 31;
    int w    = threadIdx.x >> 5;
    int row  = blockIdx.x * 8 + w;
    float klp = 0.f;
    if (row < N) {
        size_t off = (size_t)row * 128 + lane * 4;
        float4 m4 = *(const float4*)(MEAN + off);
        float4 l4 = *(const float4*)(LS + off);
        float4 n4 = *(const float4*)(NOISE + off);
        float4 e4 = make_float4(expf(l4.x), expf(l4.y), expf(l4.z), expf(l4.w));
        float4 z4 = make_float4(n4.x * e4.x + m4.x, n4.y * e4.y + m4.y,
                                n4.z * e4.z + m4.z, n4.w * e4.w + m4.w);
        float4 wa = *(const float4*)(Wc + lane * 4);
        float4 wb = *(const float4*)(Wc + 128 + lane * 4);
        float4 wn = *(const float4*)(Wn + lane * 4);
        float up = z4.x * wa.x + z4.y * wa.y + z4.z * wa.z + z4.w * wa.w;
        float vp = z4.x * wb.x + z4.y * wb.y + z4.z * wb.z + z4.w * wb.w;
        float sp = z4.x * wn.x + z4.y * wn.y + z4.z * wn.z + z4.w * wn.w;
        klp = (1.f + 2.f * l4.x - m4.x * m4.x - e4.x * e4.x)
            + (1.f + 2.f * l4.y - m4.y * m4.y - e4.y * e4.y)
            + (1.f + 2.f * l4.z - m4.z * m4.z - e4.z * e4.z)
            + (1.f + 2.f * l4.w - m4.w * m4.w - e4.w * e4.w);
        #pragma unroll
        for (int o = 16; o > 0; o >>= 1) {
            up  += __shfl_xor_sync(0xffffffffu, up,  o);
            vp  += __shfl_xor_sync(0xffffffffu, vp,  o);
            sp  += __shfl_xor_sync(0xffffffffu, sp,  o);
            klp += __shfl_xor_sync(0xffffffffu, klp, o);
        }
        if (lane == 0) {
            g_u[row] = up;
            g_v[row] = vp;
            int b = batch[row];
            atomicAdd(&g_pool[b], sp);
            atomicAdd(&g_cnt[b], 1.0f);
        }
    }
    if (lane == 0) klred[w] = (row < N) ? klp : 0.f;
    __syncthreads();
    if (threadIdx.x == 0) {
        float t = 0.f;
        #pragma unroll
        for (int i = 0; i < 8; i++) t += klred[i];
        atomicAdd(&g_acc[0], t);
    }
}

__global__ void num_k(const float* __restrict__ bridge_num,
                      const float* __restrict__ bnp,
                      float* __restrict__ out_np, int G) {
    __shared__ float red[256];
    int g = blockIdx.x * 256 + threadIdx.x;
    float d = 0.f;
    if (g < G) {
        float np = g_pool[g] / g_cnt[g] + bnp[0];
        out_np[g] = np;
        d = fabsf(np - bridge_num[g]);
    }
    red[threadIdx.x] = d;
    __syncthreads();
    for (int s = 128; s > 0; s >>= 1) {
        if (threadIdx.x < s) red[threadIdx.x] += red[threadIdx.x + s];
        __syncthreads();
    }
    if (threadIdx.x == 0) atomicAdd(&g_acc[1], red[0]);
}

__global__ void apred_k(const int* __restrict__ bidx,
                        const float* __restrict__ bcp,
                        float* __restrict__ out, int P) {
    int p = blockIdx.x * 256 + threadIdx.x;
    if (p >= P) return;
    int i = __ldg(bidx + p);
    int j = __ldg(bidx + P + p);
    float logit = g_u[i] + g_v[j] + bcp[0];
    out[p] = 1.0f / (1.0f + expf(-logit));
}

__global__ void fin_k(float* __restrict__ out, int P, int N, int G) {
    out[P]     = 0.5f * g_acc[0] / ((float)N * (float)N);
    out[P + 1] = g_acc[1] / (float)G;
}

// ---------------------------------------------------------------------------
// Launcher
// ---------------------------------------------------------------------------
extern "C" void kernel_launch(void* const* d_in, const int* in_sizes, int n_in,
                              void* d_out, int out_size) {
    const float* x          = (const float*)d_in[0];
    const int*   ei         = (const int*)  d_in[1];
    const int*   batch      = (const int*)  d_in[2];
    const float* bridge_num = (const float*)d_in[3];
    const int*   bidx       = (const int*)  d_in[4];
    const float* noise      = (const float*)d_in[5];
    const float* W1s        = (const float*)d_in[6];
    const float* b1s        = (const float*)d_in[7];
    const float* gammas     = (const float*)d_in[8];
    const float* betas      = (const float*)d_in[9];
    const float* W2s        = (const float*)d_in[10];
    const float* b2s        = (const float*)d_in[11];
    const float* Wn         = (const float*)d_in[12];
    const float* bnp        = (const float*)d_in[13];
    const float* Wc         = (const float*)d_in[14];
    const float* bcp        = (const float*)d_in[15];
    float* out = (float*)d_out;

    int N = in_sizes[0] / 128;
    int E = in_sizes[1] / 2;
    int G = in_sizes[3];
    int P = in_sizes[4] / 2;

    float *ht, *h1, *h2, *mean, *ls, *colsum, *colsq, *pool, *cnt, *acc, *b2f;
    int *deg;
    unsigned *axh, *axl, *w1h, *w1l, *w2h, *w2l, *w2sh, *w2sl;
    cudaGetSymbolAddress((void**)&ht,     g_ht);
    cudaGetSymbolAddress((void**)&h1,     g_h1);
    cudaGetSymbolAddress((void**)&h2,     g_h2);
    cudaGetSymbolAddress((void**)&mean,   g_mean);
    cudaGetSymbolAddress((void**)&ls,     g_ls);
    cudaGetSymbolAddress((void**)&colsum, g_colsum);
    cudaGetSymbolAddress((void**)&colsq,  g_colsq);
    cudaGetSymbolAddress((void**)&pool,   g_pool);
    cudaGetSymbolAddress((void**)&cnt,    g_cnt);
    cudaGetSymbolAddress((void**)&acc,    g_acc);
    cudaGetSymbolAddress((void**)&deg,    g_deg);
    cudaGetSymbolAddress((void**)&axh,    g_axh);
    cudaGetSymbolAddress((void**)&axl,    g_axl);
    cudaGetSymbolAddress((void**)&w1h,    g_w1h);
    cudaGetSymbolAddress((void**)&w1l,    g_w1l);
    cudaGetSymbolAddress((void**)&w2h,    g_w2h);
    cudaGetSymbolAddress((void**)&w2l,    g_w2l);
    cudaGetSymbolAddress((void**)&w2sh,   g_w2sh);
    cudaGetSymbolAddress((void**)&w2sl,   g_w2sl);
    cudaGetSymbolAddress((void**)&b2f,    g_b2f);

    unsigned* hth = (unsigned*)ht;                       // split ht hi
    unsigned* htl = hth + (size_t)MAXN * 256;            // split ht lo

    int rb = (N + BM - 1) / BM;
    int nb256 = (N + 255) / 256;
    int gather_blocks = (N * 32 + 255) / 256;
    const int DSM = 49152;

    // ---- build CSR + pre-split weights (once) ----
    cudaMemsetAsync(deg, 0, N * sizeof(int));
    hist_k<<<(E + 255) / 256, 256>>>(ei, E, N);
    wsplit_k<<<512, 256>>>(W1s, W2s);
    scan1_k<<<nb256, 256>>>(N);
    scan2_k<<<1, 512>>>(nb256);
    scan3_k<<<nb256, 256>>>(N);
    fill_k<<<(E + 255) / 256, 256>>>(ei, E);

    // ---- layer 0 ----
    gather_k<<<gather_blocks, 256>>>(x, N);
    cudaMemsetAsync(colsum, 0, 512 * sizeof(float));
    cudaMemsetAsync(colsq,  0, 512 * sizeof(float));
    gemmp_k<<<dim3(2, rb), 256, DSM>>>(axh, axl, 64, w1h, w1l, w1h, w1l, 64,
                                       8, b1s, 1, 0, ht, 256, 0, 0, N);
    bnfin_k<<<1, 256>>>(gammas, betas, N);
    gemm2_k<<<dim3(1, rb), 256>>>(ht, w2h, w2l, b2s, h1, N, 256, 0, 1);

    // ---- layer 1 ----
    gather_k<<<gather_blocks, 256>>>(h1, N);
    cudaMemsetAsync(colsum, 0, 512 * sizeof(float));
    cudaMemsetAsync(colsq,  0, 512 * sizeof(float));
    gemmp_k<<<dim3(2, rb), 256, DSM>>>(axh, axl, 64, w1h + 16384, w1l + 16384,
                                       w1h + 16384, w1l + 16384, 64,
                                       8, b1s + 256, 1, 0, ht, 256, 0, 0, N);
    bnfin_k<<<1, 256>>>(gammas + 256, betas + 256, N);
    gemm2_k<<<dim3(1, rb), 256>>>(ht, w2h + 16384, w2l + 16384, b2s + 128, h2, N, 256, 0, 1);

    // ---- layers 2+3 combined: gemm1 writes SPLIT ht; BN folded into W2 ----
    gather_k<<<gather_blocks, 256>>>(h2, N);
    cudaMemsetAsync(colsum, 0, 512 * sizeof(float));
    cudaMemsetAsync(colsq,  0, 512 * sizeof(float));
    gemmp_k<<<dim3(4, rb), 256, DSM>>>(axh, axl, 64,
                                       w1h + 2 * 16384, w1l + 2 * 16384,
                                       w1h + 3 * 16384, w1l + 3 * 16384, 64,
                                       8, b1s + 512, 1, 1, 0, 0, hth, htl, N);
    bnfin_k<<<1, 512>>>(gammas + 512, betas + 512, N);
    w2scale_k<<<130, 256>>>(W2s, b2s);
    gemmp_k<<<dim3(1, rb), 256, DSM>>>(hth, htl, 256, w2sh, w2sl, w2sh, w2sl, 128,
                                       16, b2f, 0, 0, mean, 128, 0, 0, N);
    gemmp_k<<<dim3(1, rb), 256, DSM>>>(hth + 128, htl + 128, 256,
                                       w2sh + 16384, w2sl + 16384,
                                       w2sh + 16384, w2sl + 16384, 128,
                                       16, b2f + 128, 0, 0, ls, 128, 0, 0, N);

    // ---- epilogue ----
    cudaMemsetAsync(pool, 0, G * sizeof(float));
    cudaMemsetAsync(cnt,  0, G * sizeof(float));
    cudaMemsetAsync(acc,  0, 2 * sizeof(float));
    z_k<<<(N + 7) / 8, 256>>>(mean, ls, noise, batch, Wn, Wc, N);
    num_k<<<(G + 255) / 256, 256>>>(bridge_num, bnp, out + P + 2, G);
    apred_k<<<(P + 255) / 256, 256>>>(bidx, bcp, out, P);
    fin_k<<<1, 1>>>(out, P, N, G);
}

// round 16
// speedup vs baseline: 1.0523x; 1.0523x over previous
#include <cuda_runtime.h>
#include <cuda_bf16.h>
#include <math.h>

// ---------------------------------------------------------------------------
// N=90000, D=H=128, 2H=256, E=1.44M, G=3000, P=675000.
// ---------------------------------------------------------------------------
#define MAXN 90112
#define MAXG 4096
#define MAXE 1500000

__device__ float    g_ht  [MAXN * 512];
__device__ float    g_h1  [MAXN * 128];
__device__ float    g_h2  [MAXN * 128];
__device__ float    g_mean[MAXN * 128];
__device__ float    g_ls  [MAXN * 128];
__device__ unsigned g_axh [MAXN * 64];     // pre-split (X+agg) hi
__device__ unsigned g_axl [MAXN * 64];     // pre-split (X+agg) lo
__device__ unsigned g_w1h [4 * 256 * 64];  // W1 pre-split [l][n][k2]
__device__ unsigned g_w1l [4 * 256 * 64];
__device__ unsigned g_w2h [4 * 128 * 128]; // W2 pre-split [l][n][k2]
__device__ unsigned g_w2l [4 * 128 * 128];
__device__ float g_u   [MAXN];
__device__ float g_v   [MAXN];
__device__ float g_colsum[512];
__device__ float g_colsq [512];
__device__ float g_scale [512];
__device__ float g_shift [512];
__device__ float g_pool[MAXG];
__device__ float g_cnt [MAXG];
__device__ float g_acc [2];
__device__ int g_deg [MAXN];
__device__ int g_off [MAXN];
__device__ int g_cur [MAXN];
__device__ int g_elist[MAXE];
__device__ int g_bsum[512];
__device__ int g_bex [512];

// ---------------------------------------------------------------------------
// bf16 split + mma helpers.
// ---------------------------------------------------------------------------
__device__ __forceinline__ void bfsplit2(float e0, float e1,
                                         unsigned& wh, unsigned& wl) {
    __nv_bfloat16 h0 = __float2bfloat16_rn(e0);
    __nv_bfloat16 h1 = __float2bfloat16_rn(e1);
    __nv_bfloat16 l0 = __float2bfloat16_rn(e0 - __bfloat162float(h0));
    __nv_bfloat16 l1 = __float2bfloat16_rn(e1 - __bfloat162float(h1));
    __nv_bfloat162 vh = __nv_bfloat162(h0, h1);
    __nv_bfloat162 vl = __nv_bfloat162(l0, l1);
    wh = *(unsigned*)&vh;
    wl = *(unsigned*)&vl;
}

__device__ __forceinline__ void mma_bf16(float4& d, const unsigned* a,
                                         unsigned b0, unsigned b1) {
    asm volatile(
        "mma.sync.aligned.m16n8k16.row.col.f32.bf16.bf16.f32 "
        "{%0,%1,%2,%3},{%4,%5,%6,%7},{%8,%9},{%0,%1,%2,%3};"
        : "+f"(d.x), "+f"(d.y), "+f"(d.z), "+f"(d.w)
        : "r"(a[0]), "r"(a[1]), "r"(a[2]), "r"(a[3]), "r"(b0), "r"(b1));
}

__device__ __forceinline__ void cp16(void* dst, const void* src) {
    unsigned d = (unsigned)__cvta_generic_to_shared(dst);
    asm volatile("cp.async.cg.shared.global [%0], [%1], 16;" :: "r"(d), "l"(src));
}
#define CP_COMMIT() asm volatile("cp.async.commit_group;")
#define CP_WAIT0()  asm volatile("cp.async.wait_group 0;")
#define CP_WAIT1()  asm volatile("cp.async.wait_group 1;")

// ---------------------------------------------------------------------------
// CSR build.
// ---------------------------------------------------------------------------
__global__ void hist_k(const int* __restrict__ ei, int E, int N) {
    int i = blockIdx.x * blockDim.x + threadIdx.x;
    if (i < E) atomicAdd(&g_deg[__ldg(ei + E + i)], 1);
}

__global__ void scan1_k(int N) {
    __shared__ int red[256];
    int i = blockIdx.x * 256 + threadIdx.x;
    red[threadIdx.x] = (i < N) ? g_deg[i] : 0;
    __syncthreads();
    for (int s = 128; s > 0; s >>= 1) {
        if (threadIdx.x < s) red[threadIdx.x] += red[threadIdx.x + s];
        __syncthreads();
    }
    if (threadIdx.x == 0) g_bsum[blockIdx.x] = red[0];
}

__global__ void scan2_k(int NB) {
    __shared__ int s0[512], s1[512];
    int t = threadIdx.x;
    int v = (t < NB) ? g_bsum[t] : 0;
    s0[t] = v;
    __syncthreads();
    int* src = s0; int* dst = s1;
    for (int o = 1; o < 512; o <<= 1) {
        int x = src[t];
        if (t >= o) x += src[t - o];
        dst[t] = x;
        __syncthreads();
        int* tmp = src; src = dst; dst = tmp;
    }
    if (t < NB) g_bex[t] = src[t] - v;
}

__global__ void scan3_k(int N) {
    __shared__ int s0[256], s1[256];
    int t = threadIdx.x;
    int i = blockIdx.x * 256 + t;
    int v = (i < N) ? g_deg[i] : 0;
    s0[t] = v;
    __syncthreads();
    int* src = s0; int* dst = s1;
    for (int o = 1; o < 256; o <<= 1) {
        int x = src[t];
        if (t >= o) x += src[t - o];
        dst[t] = x;
        __syncthreads();
        int* tmp = src; src = dst; dst = tmp;
    }
    if (i < N) {
        int off = g_bex[blockIdx.x] + src[t] - v;
        g_off[i] = off;
        g_cur[i] = off;
    }
}

__global__ void fill_k(const int* __restrict__ ei, int E) {
    int i = blockIdx.x * blockDim.x + threadIdx.x;
    if (i >= E) return;
    int s = __ldg(ei + i);
    int d = __ldg(ei + E + i);
    int p = atomicAdd(&g_cur[d], 1);
    g_elist[p] = s;
}

// ---------------------------------------------------------------------------
// Weight pre-split: W1 and W2 all layers.
// ---------------------------------------------------------------------------
__global__ void wsplit_k(const float* __restrict__ W1s,
                         const float* __restrict__ W2s) {
    int i = blockIdx.x * 256 + threadIdx.x;
    const int T1 = 4 * 64 * 256;
    if (i < T1) {
        int n = i & 255, k2 = (i >> 8) & 63, l = i >> 14;
        float e0 = W1s[l * 32768 + (2 * k2) * 256 + n];
        float e1 = W1s[l * 32768 + (2 * k2 + 1) * 256 + n];
        unsigned wh, wl;
        bfsplit2(e0, e1, wh, wl);
        g_w1h[l * 16384 + n * 64 + k2] = wh;
        g_w1l[l * 16384 + n * 64 + k2] = wl;
    } else {
        int j = i - T1;
        if (j < 4 * 128 * 128) {
            int n = j & 127, k2 = (j >> 7) & 127, l = j >> 14;
            float e0 = W2s[l * 32768 + (2 * k2) * 128 + n];
            float e1 = W2s[l * 32768 + (2 * k2 + 1) * 128 + n];
            unsigned wh, wl;
            bfsplit2(e0, e1, wh, wl);
            g_w2h[l * 16384 + n * 128 + k2] = wh;
            g_w2l[l * 16384 + n * 128 + k2] = wl;
        }
    }
}

// ---------------------------------------------------------------------------
// Gather: agg = X[own] + sum_{j in-nbrs} X[j]; write bf16 hi/lo packed.
// ---------------------------------------------------------------------------
__global__ void gather_k(const float* __restrict__ X, int N) {
    int gw   = (blockIdx.x * blockDim.x + threadIdx.x) >> 5;
    int lane = threadIdx.x & 31;
    if (gw >= N) return;
    int base = g_off[gw];
    int dg   = g_deg[gw];
    float4 acc = *(const float4*)(X + (size_t)gw * 128 + lane * 4);
    int j = 0;
    for (; j + 2 <= dg; j += 2) {
        int s0 = __ldg(g_elist + base + j);
        int s1 = __ldg(g_elist + base + j + 1);
        float4 a = *(const float4*)(X + (size_t)s0 * 128 + lane * 4);
        float4 b = *(const float4*)(X + (size_t)s1 * 128 + lane * 4);
        acc.x += a.x + b.x; acc.y += a.y + b.y;
        acc.z += a.z + b.z; acc.w += a.w + b.w;
    }
    if (j < dg) {
        int s0 = __ldg(g_elist + base + j);
        float4 a = *(const float4*)(X + (size_t)s0 * 128 + lane * 4);
        acc.x += a.x; acc.y += a.y; acc.z += a.z; acc.w += a.w;
    }
    unsigned wh0, wl0, wh1, wl1;
    bfsplit2(acc.x, acc.y, wh0, wl0);
    bfsplit2(acc.z, acc.w, wh1, wl1);
    size_t o = (size_t)gw * 64 + lane * 2;
    g_axh[o] = wh0; g_axh[o + 1] = wh1;
    g_axl[o] = wl0; g_axl[o + 1] = wl1;
}

// ---------------------------------------------------------------------------
// GEMM common: 128x128 tile, 8 warps (4m x 2n), warp 32x64, m16n8k16, BK=16.
// ---------------------------------------------------------------------------
#define BM 128
#define BN 128
#define BK 16
#define KW 136
#define SAW 20

#define MMA3(ACC, AH, AL, BH0, BH1, BL0, BL1)  \
    do { mma_bf16(ACC, AH, BH0, BH1);          \
         mma_bf16(ACC, AL, BH0, BH1);          \
         mma_bf16(ACC, AH, BL0, BL1); } while (0)

#define MMA_PHASE12(SAH, SAL, SBH, SBL)                                     \
    {                                                                       \
        unsigned ah[2][4], al[2][4];                                        \
        _Pragma("unroll")                                                   \
        for (int wm = 0; wm < 2; wm++) {                                    \
            int mr = mBase + wm * 16 + lm;                                  \
            ah[wm][0] = (SAH)[mr * 12 + lk];                                \
            ah[wm][1] = (SAH)[(mr + 8) * 12 + lk];                          \
            ah[wm][2] = (SAH)[mr * 12 + lk + 4];                            \
            ah[wm][3] = (SAH)[(mr + 8) * 12 + lk + 4];                      \
            al[wm][0] = (SAL)[mr * 12 + lk];                                \
            al[wm][1] = (SAL)[(mr + 8) * 12 + lk];                          \
            al[wm][2] = (SAL)[mr * 12 + lk + 4];                            \
            al[wm][3] = (SAL)[(mr + 8) * 12 + lk + 4];                      \
        }                                                                   \
        _Pragma("unroll")                                                   \
        for (int wn = 0; wn < 8; wn++) {                                    \
            int nc = nBase + wn * 8 + lm;                                   \
            unsigned bh0 = (SBH)[nc * 12 + lk];                             \
            unsigned bh1 = (SBH)[nc * 12 + lk + 4];                         \
            unsigned bl0 = (SBL)[nc * 12 + lk];                             \
            unsigned bl1 = (SBL)[nc * 12 + lk + 4];                         \
            _Pragma("unroll")                                               \
            for (int wm = 0; wm < 2; wm++)                                  \
                MMA3(acc[wm][wn], ah[wm], al[wm], bh0, bh1, bl0, bl1);      \
        }                                                                   \
    }

#define MMA_PHASE2(AH, AL, SBH, SBL)                                        \
    {                                                                       \
        unsigned ah[2][4], al[2][4];                                        \
        _Pragma("unroll")                                                   \
        for (int wm = 0; wm < 2; wm++) {                                    \
            int mr = mBase + wm * 16 + lm;                                  \
            ah[wm][0] = (AH)[lk * KW + mr];                                 \
            ah[wm][1] = (AH)[lk * KW + mr + 8];                             \
            ah[wm][2] = (AH)[(lk + 4) * KW + mr];                           \
            ah[wm][3] = (AH)[(lk + 4) * KW + mr + 8];                       \
            al[wm][0] = (AL)[lk * KW + mr];                                 \
            al[wm][1] = (AL)[lk * KW + mr + 8];                             \
            al[wm][2] = (AL)[(lk + 4) * KW + mr];                           \
            al[wm][3] = (AL)[(lk + 4) * KW + mr + 8];                       \
        }                                                                   \
        _Pragma("unroll")                                                   \
        for (int wn = 0; wn < 8; wn++) {                                    \
            int nc = nBase + wn * 8 + lm;                                   \
            unsigned bh0 = (SBH)[nc * 12 + lk];                             \
            unsigned bh1 = (SBH)[nc * 12 + lk + 4];                         \
            unsigned bl0 = (SBL)[nc * 12 + lk];                             \
            unsigned bl1 = (SBL)[nc * 12 + lk + 4];                         \
            _Pragma("unroll")                                               \
            for (int wm = 0; wm < 2; wm++)                                  \
                MMA3(acc[wm][wn], ah[wm], al[wm], bh0, bh1, bl0, bl1);      \
        }                                                                   \
    }

// ---------------------------------------------------------------------------
// gemm1-style pre-split GEMM: OUT = A_split @ W1_split^T + bias; fused stats.
// ---------------------------------------------------------------------------
__global__ void __launch_bounds__(256) gemmp_k(
    const unsigned* __restrict__ ah, const unsigned* __restrict__ al,
    const unsigned* __restrict__ whA, const unsigned* __restrict__ wlA,
    const unsigned* __restrict__ whB, const unsigned* __restrict__ wlB,
    const float* __restrict__ bias, float* __restrict__ OUT,
    int N, int ldo) {
    extern __shared__ unsigned dsm[];
    int tid  = threadIdx.x;
    int row0 = blockIdx.y * BM;
    int n0   = blockIdx.x * BN;
    const unsigned* wsh = (n0 < 256) ? whA : whB;
    const unsigned* wsl = (n0 < 256) ? wlA : wlB;
    int nbase = (n0 < 256) ? n0 : (n0 - 256);
    int lane = tid & 31, wid = tid >> 5;
    int lk = lane & 3, lm = lane >> 2;
    int warpM = wid & 3, warpN = wid >> 2;
    int mBase = warpM * 32, nBase = warpN * 64;
    float4 acc[2][8];
    #pragma unroll
    for (int i = 0; i < 2; i++)
        #pragma unroll
        for (int j = 0; j < 8; j++) acc[i][j] = make_float4(0.f,0.f,0.f,0.f);

    auto issue = [&](int t, int st) {
        unsigned* base = dsm + st * 6144;
        int kw = t * 8;
        #pragma unroll
        for (int q = 0; q < 4; q++) {
            int c = q * 256 + tid;
            int arr = c >> 8;
            int r   = c & 255;
            int m   = r >> 1;
            int half = r & 1;
            unsigned* dst = base + arr * 1536 + m * 12 + half * 4;
            const unsigned* src;
            if (arr == 0)      src = ah + (size_t)(row0 + m) * 64 + kw + half * 4;
            else if (arr == 1) src = al + (size_t)(row0 + m) * 64 + kw + half * 4;
            else if (arr == 2) src = wsh + (size_t)(nbase + m) * 64 + kw + half * 4;
            else               src = wsl + (size_t)(nbase + m) * 64 + kw + half * 4;
            cp16(dst, src);
        }
        CP_COMMIT();
    };

    issue(0, 0);
    #pragma unroll 1
    for (int t = 0; t < 8; t++) {
        int st = t & 1;
        if (t + 1 < 8) {
            issue(t + 1, st ^ 1);
            CP_WAIT1();
        } else {
            CP_WAIT0();
        }
        __syncthreads();
        unsigned* B0 = dsm + st * 6144;
        MMA_PHASE12(B0, B0 + 1536, B0 + 3072, B0 + 4608)
        __syncthreads();
    }

    float psx[8]={}, psy[8]={}, pqx[8]={}, pqy[8]={};
    #pragma unroll
    for (int wn = 0; wn < 8; wn++) {
        int col = n0 + nBase + wn * 8 + 2 * lk;
        float bx = bias[col], by = bias[col + 1];
        #pragma unroll
        for (int wm = 0; wm < 2; wm++) {
            float4 d = acc[wm][wn];
            int ra = row0 + mBase + wm * 16 + lm;
            int rb = ra + 8;
            float ox = d.x + bx, oy = d.y + by;
            float oz = d.z + bx, ow = d.w + by;
            if (ra < N) {
                *(float2*)(OUT + (size_t)ra * ldo + col) = make_float2(ox, oy);
                psx[wn] += ox; psy[wn] += oy;
                pqx[wn] += ox * ox; pqy[wn] += oy * oy;
            }
            if (rb < N) {
                *(float2*)(OUT + (size_t)rb * ldo + col) = make_float2(oz, ow);
                psx[wn] += oz; psy[wn] += ow;
                pqx[wn] += oz * oz; pqy[wn] += ow * ow;
            }
        }
    }
    #pragma unroll
    for (int wn = 0; wn < 8; wn++) {
        #pragma unroll
        for (int o = 4; o <= 16; o <<= 1) {
            psx[wn] += __shfl_xor_sync(0xffffffffu, psx[wn], o);
            psy[wn] += __shfl_xor_sync(0xffffffffu, psy[wn], o);
            pqx[wn] += __shfl_xor_sync(0xffffffffu, pqx[wn], o);
            pqy[wn] += __shfl_xor_sync(0xffffffffu, pqy[wn], o);
        }
    }
    if (lane < 4) {
        #pragma unroll
        for (int wn = 0; wn < 8; wn++) {
            int col = n0 + nBase + wn * 8 + 2 * lane;
            atomicAdd(&g_colsum[col],     psx[wn]);
            atomicAdd(&g_colsum[col + 1], psy[wn]);
            atomicAdd(&g_colsq[col],      pqx[wn]);
            atomicAdd(&g_colsq[col + 1],  pqy[wn]);
        }
    }
}

__global__ void bnfin_k(const float* __restrict__ gamma,
                        const float* __restrict__ beta, int N) {
    int c = blockIdx.x * blockDim.x + threadIdx.x;
    float invN = 1.0f / (float)N;
    float mu  = g_colsum[c] * invN;
    float var = g_colsq[c] * invN - mu * mu;
    float sc  = gamma[c] * rsqrtf(var + 1e-5f);
    g_scale[c] = sc;
    g_shift[c] = beta[c] - mu * sc;
}

// ---------------------------------------------------------------------------
// GEMM2 (dual-output): OUT = BN(HT[:,koff:+256]) [relu] @ W2 + b2.
// blockIdx.x selects the {W2, bias, OUT, koff} set (tail-wave merge).
// ---------------------------------------------------------------------------
__global__ void __launch_bounds__(256) gemm2_k(
    const float* __restrict__ HT,
    const unsigned* __restrict__ w2h0, const unsigned* __restrict__ w2l0,
    const float* __restrict__ bias0, float* __restrict__ OUT0,
    const unsigned* __restrict__ w2h1, const unsigned* __restrict__ w2l1,
    const float* __restrict__ bias1, float* __restrict__ OUT1,
    int N, int ldh, int koff0, int koff1, int relu) {
    __shared__ unsigned Ah[8 * KW], Al[8 * KW];
    __shared__ unsigned Sbh[2 * 1536], Sbl[2 * 1536];
    __shared__ float Sa[128 * SAW];
    int tid  = threadIdx.x;
    int row0 = blockIdx.y * BM;
    int alt  = blockIdx.x;
    const unsigned* w2h = alt ? w2h1 : w2h0;
    const unsigned* w2l = alt ? w2l1 : w2l0;
    const float* bias   = alt ? bias1 : bias0;
    float* OUT          = alt ? OUT1 : OUT0;
    int koff            = alt ? koff1 : koff0;
    int lane = tid & 31, wid = tid >> 5;
    int lk = lane & 3, lm = lane >> 2;
    int warpM = wid & 3, warpN = wid >> 2;
    int mBase = warpM * 32, nBase = warpN * 64;
    float4 acc[2][8];
    #pragma unroll
    for (int i = 0; i < 2; i++)
        #pragma unroll
        for (int j = 0; j < 8; j++) acc[i][j] = make_float4(0.f,0.f,0.f,0.f);

    auto issue = [&](int kk, int st) {
        #pragma unroll
        for (int q = 0; q < 4; q++) {
            int c = q * 256 + tid;
            if (c < 512) {
                int m = c >> 2, kq = (c & 3) * 4;
                cp16(Sa + m * SAW + kq,
                     HT + (size_t)(row0 + m) * ldh + koff + kk + kq);
            } else {
                int c2 = c - 512;
                int arr = c2 >> 8;
                int r = c2 & 255;
                int n = r >> 1, half = r & 1;
                const unsigned* src = (arr ? w2l : w2h)
                    + (size_t)n * 128 + kk / 2 + half * 4;
                unsigned* dst = (arr ? Sbl : Sbh) + st * 1536 + n * 12 + half * 4;
                cp16(dst, src);
            }
        }
        CP_COMMIT();
    };
    issue(0, 0);

    #pragma unroll 1
    for (int kk = 0; kk < 256; kk += BK) {
        int st = (kk >> 4) & 1;
        CP_WAIT0();
        __syncthreads();
        #pragma unroll
        for (int h = 0; h < 2; h++) {
            int idx = h * 256 + tid;
            int m  = idx & 127;
            int kq = (idx >> 7) * 4;
            float4 a = *(float4*)(Sa + m * SAW + kq);
            float4 sc4 = *(const float4*)(g_scale + koff + kk + kq);
            float4 sh4 = *(const float4*)(g_shift + koff + kk + kq);
            a.x = a.x * sc4.x + sh4.x;
            a.y = a.y * sc4.y + sh4.y;
            a.z = a.z * sc4.z + sh4.z;
            a.w = a.w * sc4.w + sh4.w;
            if (relu) {
                a.x = fmaxf(a.x, 0.f); a.y = fmaxf(a.y, 0.f);
                a.z = fmaxf(a.z, 0.f); a.w = fmaxf(a.w, 0.f);
            }
            unsigned wh0, wl0, wh1, wl1;
            bfsplit2(a.x, a.y, wh0, wl0);
            bfsplit2(a.z, a.w, wh1, wl1);
            int aw = (kq >> 1) * KW + m;
            Ah[aw] = wh0; Al[aw] = wl0;
            Ah[aw + KW] = wh1; Al[aw + KW] = wl1;
        }
        __syncthreads();
        if (kk + BK < 256) issue(kk + BK, st ^ 1);
        MMA_PHASE2(Ah, Al, Sbh + st * 1536, Sbl + st * 1536)
    }

    #pragma unroll
    for (int wn = 0; wn < 8; wn++) {
        int col = nBase + wn * 8 + 2 * lk;
        float bx = bias[col], by = bias[col + 1];
        #pragma unroll
        for (int wm = 0; wm < 2; wm++) {
            float4 d = acc[wm][wn];
            int ra = row0 + mBase + wm * 16 + lm;
            int rb = ra + 8;
            if (ra < N)
                *(float2*)(OUT + (size_t)ra * 128 + col) = make_float2(d.x + bx, d.y + by);
            if (rb < N)
                *(float2*)(OUT + (size_t)rb * 128 + col) = make_float2(d.z + bx, d.w + by);
        }
    }
}

// ---------------------------------------------------------------------------
// z epilogue and small kernels.
// ---------------------------------------------------------------------------
__global__ void z_k(const float* __restrict__ MEAN, const float* __restrict__ LS,
                    const float* __restrict__ NOISE, const int* __restrict__ batch,
                    const float* __restrict__ Wn, const float* __restrict__ Wc,
                    int N) {
    __shared__ float klred[8];
    int lane = threadIdx.x & 31;
    int w    = threadIdx.x >> 5;
    int row  = blockIdx.x * 8 + w;
    float klp = 0.f;
    if (row < N) {
        size_t off = (size_t)row * 128 + lane * 4;
        float4 m4 = *(const float4*)(MEAN + off);
        float4 l4 = *(const float4*)(LS + off);
        float4 n4 = *(const float4*)(NOISE + off);
        float4 e4 = make_float4(expf(l4.x), expf(l4.y), expf(l4.z), expf(l4.w));
        float4 z4 = make_float4(n4.x * e4.x + m4.x, n4.y * e4.y + m4.y,
                                n4.z * e4.z + m4.z, n4.w * e4.w + m4.w);
        float4 wa = *(const float4*)(Wc + lane * 4);
        float4 wb = *(const float4*)(Wc + 128 + lane * 4);
        float4 wn = *(const float4*)(Wn + lane * 4);
        float up = z4.x * wa.x + z4.y * wa.y + z4.z * wa.z + z4.w * wa.w;
        float vp = z4.x * wb.x + z4.y * wb.y + z4.z * wb.z + z4.w * wb.w;
        float sp = z4.x * wn.x + z4.y * wn.y + z4.z * wn.z + z4.w * wn.w;
        klp = (1.f + 2.f * l4.x - m4.x * m4.x - e4.x * e4.x)
            + (1.f + 2.f * l4.y - m4.y * m4.y - e4.y * e4.y)
            + (1.f + 2.f * l4.z - m4.z * m4.z - e4.z * e4.z)
            + (1.f + 2.f * l4.w - m4.w * m4.w - e4.w * e4.w);
        #pragma unroll
        for (int o = 16; o > 0; o >>= 1) {
            up  += __shfl_xor_sync(0xffffffffu, up,  o);
            vp  += __shfl_xor_sync(0xffffffffu, vp,  o);
            sp  += __shfl_xor_sync(0xffffffffu, sp,  o);
            klp += __shfl_xor_sync(0xffffffffu, klp, o);
        }
        if (lane == 0) {
            g_u[row] = up;
            g_v[row] = vp;
            int b = batch[row];
            atomicAdd(&g_pool[b], sp);
            atomicAdd(&g_cnt[b], 1.0f);
        }
    }
    if (lane == 0) klred[w] = (row < N) ? klp : 0.f;
    __syncthreads();
    if (threadIdx.x == 0) {
        float t = 0.f;
        #pragma unroll
        for (int i = 0; i < 8; i++) t += klred[i];
        atomicAdd(&g_acc[0], t);
    }
}

__global__ void num_k(const float* __restrict__ bridge_num,
                      const float* __restrict__ bnp,
                      float* __restrict__ out_np, int G) {
    __shared__ float red[256];
    int g = blockIdx.x * 256 + threadIdx.x;
    float d = 0.f;
    if (g < G) {
        float np = g_pool[g] / g_cnt[g] + bnp[0];
        out_np[g] = np;
        d = fabsf(np - bridge_num[g]);
    }
    red[threadIdx.x] = d;
    __syncthreads();
    for (int s = 128; s > 0; s >>= 1) {
        if (threadIdx.x < s) red[threadIdx.x] += red[threadIdx.x + s];
        __syncthreads();
    }
    if (threadIdx.x == 0) atomicAdd(&g_acc[1], red[0]);
}

__global__ void apred_k(const int* __restrict__ bidx,
                        const float* __restrict__ bcp,
                        float* __restrict__ out, int P) {
    int p = blockIdx.x * 256 + threadIdx.x;
    if (p >= P) return;
    int i = __ldg(bidx + p);
    int j = __ldg(bidx + P + p);
    float logit = g_u[i] + g_v[j] + bcp[0];
    out[p] = 1.0f / (1.0f + expf(-logit));
}

__global__ void fin_k(float* __restrict__ out, int P, int N, int G) {
    out[P]     = 0.5f * g_acc[0] / ((float)N * (float)N);
    out[P + 1] = g_acc[1] / (float)G;
}

// ---------------------------------------------------------------------------
// Launcher
// ---------------------------------------------------------------------------
extern "C" void kernel_launch(void* const* d_in, const int* in_sizes, int n_in,
                              void* d_out, int out_size) {
    const float* x          = (const float*)d_in[0];
    const int*   ei         = (const int*)  d_in[1];
    const int*   batch      = (const int*)  d_in[2];
    const float* bridge_num = (const float*)d_in[3];
    const int*   bidx       = (const int*)  d_in[4];
    const float* noise      = (const float*)d_in[5];
    const float* W1s        = (const float*)d_in[6];
    const float* b1s        = (const float*)d_in[7];
    const float* gammas     = (const float*)d_in[8];
    const float* betas      = (const float*)d_in[9];
    const float* W2s        = (const float*)d_in[10];
    const float* b2s        = (const float*)d_in[11];
    const float* Wn         = (const float*)d_in[12];
    const float* bnp        = (const float*)d_in[13];
    const float* Wc         = (const float*)d_in[14];
    const float* bcp        = (const float*)d_in[15];
    float* out = (float*)d_out;

    int N = in_sizes[0] / 128;
    int E = in_sizes[1] / 2;
    int G = in_sizes[3];
    int P = in_sizes[4] / 2;

    float *ht, *h1, *h2, *mean, *ls, *colsum, *colsq, *pool, *cnt, *acc;
    int *deg;
    unsigned *axh, *axl, *w1h, *w1l, *w2h, *w2l;
    cudaGetSymbolAddress((void**)&ht,     g_ht);
    cudaGetSymbolAddress((void**)&h1,     g_h1);
    cudaGetSymbolAddress((void**)&h2,     g_h2);
    cudaGetSymbolAddress((void**)&mean,   g_mean);
    cudaGetSymbolAddress((void**)&ls,     g_ls);
    cudaGetSymbolAddress((void**)&colsum, g_colsum);
    cudaGetSymbolAddress((void**)&colsq,  g_colsq);
    cudaGetSymbolAddress((void**)&pool,   g_pool);
    cudaGetSymbolAddress((void**)&cnt,    g_cnt);
    cudaGetSymbolAddress((void**)&acc,    g_acc);
    cudaGetSymbolAddress((void**)&deg,    g_deg);
    cudaGetSymbolAddress((void**)&axh,    g_axh);
    cudaGetSymbolAddress((void**)&axl,    g_axl);
    cudaGetSymbolAddress((void**)&w1h,    g_w1h);
    cudaGetSymbolAddress((void**)&w1l,    g_w1l);
    cudaGetSymbolAddress((void**)&w2h,    g_w2h);
    cudaGetSymbolAddress((void**)&w2l,    g_w2l);

    int rb = (N + BM - 1) / BM;
    int nb256 = (N + 255) / 256;
    int gather_blocks = (N * 32 + 255) / 256;
    const int DSM = 49152;

    // ---- build CSR + pre-split weights (once) ----
    cudaMemsetAsync(deg, 0, N * sizeof(int));
    hist_k<<<(E + 255) / 256, 256>>>(ei, E, N);
    wsplit_k<<<512, 256>>>(W1s, W2s);
    scan1_k<<<nb256, 256>>>(N);
    scan2_k<<<1, 512>>>(nb256);
    scan3_k<<<nb256, 256>>>(N);
    fill_k<<<(E + 255) / 256, 256>>>(ei, E);

    // ---- layer 0 ----
    gather_k<<<gather_blocks, 256>>>(x, N);
    cudaMemsetAsync(colsum, 0, 512 * sizeof(float));
    cudaMemsetAsync(colsq,  0, 512 * sizeof(float));
    gemmp_k<<<dim3(2, rb), 256, DSM>>>(axh, axl, w1h, w1l, w1h, w1l, b1s, ht, N, 256);
    bnfin_k<<<1, 256>>>(gammas, betas, N);
    gemm2_k<<<dim3(1, rb), 256>>>(ht, w2h, w2l, b2s, h1,
                                  w2h, w2l, b2s, h1, N, 256, 0, 0, 1);

    // ---- layer 1 ----
    gather_k<<<gather_blocks, 256>>>(h1, N);
    cudaMemsetAsync(colsum, 0, 512 * sizeof(float));
    cudaMemsetAsync(colsq,  0, 512 * sizeof(float));
    gemmp_k<<<dim3(2, rb), 256, DSM>>>(axh, axl, w1h + 16384, w1l + 16384,
                                       w1h + 16384, w1l + 16384, b1s + 256, ht, N, 256);
    bnfin_k<<<1, 256>>>(gammas + 256, betas + 256, N);
    gemm2_k<<<dim3(1, rb), 256>>>(ht, w2h + 16384, w2l + 16384, b2s + 128, h2,
                                  w2h + 16384, w2l + 16384, b2s + 128, h2,
                                  N, 256, 0, 0, 1);

    // ---- layers 2+3 combined (shared A), dual-output final gemm2 ----
    gather_k<<<gather_blocks, 256>>>(h2, N);
    cudaMemsetAsync(colsum, 0, 512 * sizeof(float));
    cudaMemsetAsync(colsq,  0, 512 * sizeof(float));
    gemmp_k<<<dim3(4, rb), 256, DSM>>>(axh, axl,
                                       w1h + 2 * 16384, w1l + 2 * 16384,
                                       w1h + 3 * 16384, w1l + 3 * 16384,
                                       b1s + 512, ht, N, 512);
    bnfin_k<<<1, 512>>>(gammas + 512, betas + 512, N);
    gemm2_k<<<dim3(2, rb), 256>>>(ht, w2h + 2 * 16384, w2l + 2 * 16384, b2s + 256, mean,
                                  w2h + 3 * 16384, w2l + 3 * 16384, b2s + 384, ls,
                                  N, 512, 0, 256, 0);

    // ---- epilogue ----
    cudaMemsetAsync(pool, 0, G * sizeof(float));
    cudaMemsetAsync(cnt,  0, G * sizeof(float));
    cudaMemsetAsync(acc,  0, 2 * sizeof(float));
    z_k<<<(N + 7) / 8, 256>>>(mean, ls, noise, batch, Wn, Wc, N);
    num_k<<<(G + 255) / 256, 256>>>(bridge_num, bnp, out + P + 2, G);
    apred_k<<<(P + 255) / 256, 256>>>(bidx, bcp, out, P);
    fin_k<<<1, 1>>>(out, P, N, G);
}